// round 4
// baseline (speedup 1.0000x reference)
#include <cuda_runtime.h>
#include <cuda_bf16.h>
#include <math.h>

#define DIMK 1024
#define CC   128
#define BB   8
#define TT   2048
#define ROWS (BB*TT)   // 16384

typedef unsigned long long ull;

// ------------------------- device scratch (no allocs allowed) -------------
__device__ float g_Q [ROWS*CC];
__device__ float g_K [ROWS*CC];   // normalized k
__device__ float g_V [ROWS*CC];
__device__ float g_G [ROWS*CC];
__device__ float g_O [ROWS*CC];
__device__ float g_Al[ROWS];
__device__ float g_Be[ROWS];

__device__ __forceinline__ float sigmoidf_(float x) { return 1.0f / (1.0f + expf(-x)); }

// ---- packed f32x2 helpers ----
__device__ __forceinline__ ull pack2(float lo, float hi) {
    ull r; asm("mov.b64 %0, {%1, %2};" : "=l"(r) : "f"(lo), "f"(hi)); return r;
}
__device__ __forceinline__ void unpack2(ull v, float& lo, float& hi) {
    asm("mov.b64 {%0, %1}, %2;" : "=f"(lo), "=f"(hi) : "l"(v));
}
__device__ __forceinline__ ull fma2(ull a, ull b, ull c) {
    ull d; asm("fma.rn.f32x2 %0, %1, %2, %3;" : "=l"(d) : "l"(a), "l"(b), "l"(c)); return d;
}
__device__ __forceinline__ ull mul2(ull a, ull b) {
    ull d; asm("mul.rn.f32x2 %0, %1, %2;" : "=l"(d) : "l"(a), "l"(b)); return d;
}

// ===========================================================================
// Kernel 1: projections  q,k,v,g = x @ W + b  (f32x2 SGEMM, 128x128x16)
// ===========================================================================
__global__ __launch_bounds__(256) void proj_gemm(
    const float* __restrict__ x,
    const float* __restrict__ Wq, const float* __restrict__ Wk,
    const float* __restrict__ Wv, const float* __restrict__ Wg,
    const float* __restrict__ bq, const float* __restrict__ bk,
    const float* __restrict__ bv, const float* __restrict__ bg)
{
    __shared__ __align__(16) float As2[16][256];
    __shared__ __align__(16) float Bs[16][128];

    const int mid  = blockIdx.y;
    const float* W    = (mid == 0) ? Wq : (mid == 1) ? Wk : (mid == 2) ? Wv : Wg;
    const float* bias = (mid == 0) ? bq : (mid == 1) ? bk : (mid == 2) ? bv : bg;
    float* outp       = (mid == 0) ? g_Q : (mid == 1) ? g_K : (mid == 2) ? g_V : g_G;

    const int row0 = blockIdx.x * 128;
    const int tid  = threadIdx.x;
    const int tx   = tid & 15;
    const int ty   = tid >> 4;
    const int lr   = tid >> 2;
    const int lc   = (tid & 3) * 4;

    ull acc[8][4];
#pragma unroll
    for (int m = 0; m < 8; ++m)
#pragma unroll
        for (int n = 0; n < 4; ++n) acc[m][n] = 0ull;

    for (int k0 = 0; k0 < DIMK; k0 += 16) {
#pragma unroll
        for (int h = 0; h < 2; ++h) {
            int r = lr + h * 64;
            float4 a4 = *(const float4*)(x + (size_t)(row0 + r) * DIMK + k0 + lc);
            *(float2*)&As2[lc + 0][2 * r] = make_float2(a4.x, a4.x);
            *(float2*)&As2[lc + 1][2 * r] = make_float2(a4.y, a4.y);
            *(float2*)&As2[lc + 2][2 * r] = make_float2(a4.z, a4.z);
            *(float2*)&As2[lc + 3][2 * r] = make_float2(a4.w, a4.w);
        }
#pragma unroll
        for (int h = 0; h < 2; ++h) {
            int kk = (tid >> 5) + h * 8;
            int n  = (tid & 31) * 4;
            *(float4*)&Bs[kk][n] = *(const float4*)(W + (size_t)(k0 + kk) * CC + n);
        }
        __syncthreads();
#pragma unroll
        for (int kk = 0; kk < 16; ++kk) {
            const ulonglong2* ap = (const ulonglong2*)&As2[kk][2 * (ty * 8)];
            const ulonglong2* bp = (const ulonglong2*)&Bs[kk][tx * 8];
            ulonglong2 a01 = ap[0], a23 = ap[1], a45 = ap[2], a67 = ap[3];
            ulonglong2 b01 = bp[0], b23 = bp[1];
            ull ar[8] = {a01.x, a01.y, a23.x, a23.y, a45.x, a45.y, a67.x, a67.y};
            ull br[4] = {b01.x, b01.y, b23.x, b23.y};
#pragma unroll
            for (int m = 0; m < 8; ++m)
#pragma unroll
                for (int n = 0; n < 4; ++n)
                    acc[m][n] = fma2(ar[m], br[n], acc[m][n]);
        }
        __syncthreads();
    }

#pragma unroll
    for (int m = 0; m < 8; ++m) {
        int row = row0 + ty * 8 + m;
#pragma unroll
        for (int n = 0; n < 4; ++n) {
            int col = tx * 8 + 2 * n;
            float e0, e1; unpack2(acc[m][n], e0, e1);
            float v0 = e0 + bias[col];
            float v1 = e1 + bias[col + 1];
            if (mid == 3) { v0 = sigmoidf_(v0); v1 = sigmoidf_(v1); }
            *(float2*)&outp[(size_t)row * CC + col] = make_float2(v0, v1);
        }
    }
}

// ===========================================================================
// Kernel 2: alpha/beta
// ===========================================================================
__global__ __launch_bounds__(256) void ab_kernel(
    const float* __restrict__ x,
    const float* __restrict__ Wa, const float* __restrict__ ba,
    const float* __restrict__ Wb, const float* __restrict__ bb)
{
    const int warp = threadIdx.x >> 5, lane = threadIdx.x & 31;
    const int row  = blockIdx.x * 8 + warp;
    const float* xr = x + (size_t)row * DIMK;
    float accA = 0.0f, accB = 0.0f;
#pragma unroll
    for (int it = 0; it < 8; ++it) {
        int kidx = it * 128 + lane * 4;
        float4 xv = *(const float4*)(xr + kidx);
        float4 wa = *(const float4*)(Wa + kidx);
        float4 wb = *(const float4*)(Wb + kidx);
        accA += xv.x * wa.x + xv.y * wa.y + xv.z * wa.z + xv.w * wa.w;
        accB += xv.x * wb.x + xv.y * wb.y + xv.z * wb.z + xv.w * wb.w;
    }
#pragma unroll
    for (int o = 16; o; o >>= 1) {
        accA += __shfl_xor_sync(0xffffffffu, accA, o);
        accB += __shfl_xor_sync(0xffffffffu, accB, o);
    }
    if (lane == 0) {
        g_Al[row] = sigmoidf_(accA + ba[0]);
        g_Be[row] = sigmoidf_(accB + bb[0]);
    }
}

// ===========================================================================
// Kernel 3: normalize k rows
// ===========================================================================
__global__ __launch_bounds__(256) void knorm_kernel()
{
    const int warp = threadIdx.x >> 5, lane = threadIdx.x & 31;
    const int row  = blockIdx.x * 8 + warp;
    float* kp = g_K + (size_t)row * CC + lane * 4;
    float4 kv = *(float4*)kp;
    float ss = kv.x * kv.x + kv.y * kv.y + kv.z * kv.z + kv.w * kv.w;
#pragma unroll
    for (int o = 16; o; o >>= 1) ss += __shfl_xor_sync(0xffffffffu, ss, o);
    float scale = 1.0f / fmaxf(sqrtf(ss), 1e-12f);
    kv.x *= scale; kv.y *= scale; kv.z *= scale; kv.w *= scale;
    *(float4*)kp = kv;
}

// ===========================================================================
// Kernel 4: gated-delta scan, one CTA (512 threads) per batch.
// Threads 0..255   (A, warps 0..7):  lane pair (2m,2m+1) of warp w owns the
//                                    two 64-wide halves of S row (16w+m).
// Threads 256..511 (B, warps 8..15): same layout for S^T rows.
// State packed f32x2 (32 ull/thread). S_true = c*S_hat, c block-uniform, so
// the rank-1 update is one fma2 per packed pair. Rescale when c < 1e-10.
// ===========================================================================
__global__ __launch_bounds__(512, 1) void scan_kernel()
{
    const int b    = blockIdx.x;
    const int tid  = threadIdx.x;
    const bool isA = (tid < 256);
    const int st   = isA ? tid : tid - 256;
    const int row  = st >> 1;         // 0..127
    const int half = st & 1;          // which 64-wide half
    const int lane = tid & 31;
    const int warp = tid >> 5;        // 0..15
    const int hoff = half * 64;

    __shared__ __align__(16) float k_sh[2][128], q_sh[2][128];
    __shared__ __align__(16) float v_sh[2][128], g_sh[2][128];
    __shared__ __align__(16) float u_sh[128];
    __shared__ float qup[8];
    __shared__ float2 ab_sh[2];

    ull Sp[32];                        // 64 floats of one half-row
#pragma unroll
    for (int j = 0; j < 32; ++j) Sp[j] = 0ull;
    float c = 1.0f;

    const size_t base = (size_t)b * TT * CC;
    const float* Ab = g_Al + (size_t)b * TT;
    const float* Bb = g_Be + (size_t)b * TT;
    float*       Ob = g_O + base;

    // staging: 512 threads cover 4 vectors x 128 floats
    const int arr = tid >> 7;          // 0:k 1:q 2:v 3:g
    const int idx = tid & 127;
    const float* stage_src =
        (arr == 0 ? g_K : arr == 1 ? g_Q : arr == 2 ? g_V : g_G) + base + idx;
    float* stage_dst =
        (arr == 0 ? &k_sh[0][0] : arr == 1 ? &q_sh[0][0] :
         arr == 2 ? &v_sh[0][0] : &g_sh[0][0]) + idx;

    float s = stage_src[0];
    float2 abr = make_float2(0.f, 0.f);
    if (tid == 0) abr = make_float2(Ab[0], Bb[0]);

    int p = 0;
    for (int t = 0; t < TT; ++t) {
        stage_dst[p * 128] = s;
        if (tid == 0) ab_sh[p] = abr;
        __syncthreads();

        // prefetch t+1 under the math below
        if (t + 1 < TT) {
            s = stage_src[(size_t)(t + 1) * CC];
            if (tid == 0) abr = make_float2(Ab[t + 1], Bb[t + 1]);
        }

        const float aa  = ab_sh[p].x;
        const float bbv = ab_sh[p].y;

        // half-row dot: A vs k, B vs q (16 LDS.128, 32 fma2)
        const ulonglong2* xp =
            (const ulonglong2*)((isA ? k_sh[p] : q_sh[p]) + hoff);
        ull a0 = 0ull, a1 = 0ull, a2 = 0ull, a3 = 0ull;
#pragma unroll
        for (int j = 0; j < 8; ++j) {
            ulonglong2 xa = xp[2 * j], xb = xp[2 * j + 1];
            a0 = fma2(Sp[4 * j + 0], xa.x, a0);
            a1 = fma2(Sp[4 * j + 1], xa.y, a1);
            a2 = fma2(Sp[4 * j + 2], xb.x, a2);
            a3 = fma2(Sp[4 * j + 3], xb.y, a3);
        }
        float f0, f1, f2, f3, f4, f5, f6, f7;
        unpack2(a0, f0, f1); unpack2(a1, f2, f3);
        unpack2(a2, f4, f5); unpack2(a3, f6, f7);
        float d = ((f0 + f1) + (f2 + f3)) + ((f4 + f5) + (f6 + f7));
        d += __shfl_xor_sync(0xffffffffu, d, 1);   // combine the two halves

        float u = 0.0f, phat = 0.0f;
        if (isA) {
            const float Sk = c * d;
            u = bbv * v_sh[p][row] - aa * bbv * Sk;
            if (half == 0) u_sh[row] = u;
            // q^T u partial: every row appears twice in the warp -> x0.5 later
            float pq = q_sh[p][row] * u;
#pragma unroll
            for (int o = 16; o; o >>= 1) pq += __shfl_xor_sync(0xffffffffu, pq, o);
            if (lane == 0) qup[warp] = pq;
        } else {
            phat = d;
        }
        __syncthreads();

        const float cn   = aa * c;
        const float winv = 1.0f / cn;

        if (isA) {
            // S_hat[row][half] += (u/cn) * k[half]
            const float w = u * winv;
            const ull w2 = pack2(w, w);
            const ulonglong2* kp2 = (const ulonglong2*)(k_sh[p] + hoff);
#pragma unroll
            for (int j = 0; j < 8; ++j) {
                ulonglong2 ka = kp2[2 * j], kb = kp2[2 * j + 1];
                Sp[4 * j + 0] = fma2(w2, ka.x, Sp[4 * j + 0]);
                Sp[4 * j + 1] = fma2(w2, ka.y, Sp[4 * j + 1]);
                Sp[4 * j + 2] = fma2(w2, kb.x, Sp[4 * j + 2]);
                Sp[4 * j + 3] = fma2(w2, kb.y, Sp[4 * j + 3]);
            }
        } else {
            const float qu = 0.5f * (((qup[0] + qup[1]) + (qup[2] + qup[3])) +
                                     ((qup[4] + qup[5]) + (qup[6] + qup[7])));
            const float kj = k_sh[p][row];
            const float o  = aa * (c * phat) + qu * kj;   // (q^T S_new)[row]
            if (half == 0) Ob[(size_t)t * CC + row] = o * g_sh[p][row];
            // S_hat^T[row][half] += (k_row/cn) * u[half]
            const float kw = kj * winv;
            const ull kw2 = pack2(kw, kw);
            const ulonglong2* up2 = (const ulonglong2*)(u_sh + hoff);
#pragma unroll
            for (int j = 0; j < 8; ++j) {
                ulonglong2 ua = up2[2 * j], ub = up2[2 * j + 1];
                Sp[4 * j + 0] = fma2(kw2, ua.x, Sp[4 * j + 0]);
                Sp[4 * j + 1] = fma2(kw2, ua.y, Sp[4 * j + 1]);
                Sp[4 * j + 2] = fma2(kw2, ub.x, Sp[4 * j + 2]);
                Sp[4 * j + 3] = fma2(kw2, ub.y, Sp[4 * j + 3]);
            }
        }

        c = cn;
        if (c < 1e-10f) {
            const ull c2 = pack2(c, c);
#pragma unroll
            for (int j = 0; j < 32; ++j) Sp[j] = mul2(Sp[j], c2);
            c = 1.0f;
        }
        p ^= 1;
    }
}

// ===========================================================================
// Kernel 5: out = O @ Wo + bo   (f32x2 SGEMM)
// ===========================================================================
__global__ __launch_bounds__(256) void out_gemm(
    const float* __restrict__ Wo, const float* __restrict__ bo,
    float* __restrict__ out)
{
    __shared__ __align__(16) float As2[16][256];
    __shared__ __align__(16) float Bs[16][128];

    const int row0 = blockIdx.x * 128;
    const int col0 = blockIdx.y * 128;
    const int tid  = threadIdx.x;
    const int tx   = tid & 15;
    const int ty   = tid >> 4;
    const int lr   = tid >> 2;
    const int lc   = (tid & 3) * 4;

    ull acc[8][4];
#pragma unroll
    for (int m = 0; m < 8; ++m)
#pragma unroll
        for (int n = 0; n < 4; ++n) acc[m][n] = 0ull;

    for (int k0 = 0; k0 < CC; k0 += 16) {
#pragma unroll
        for (int h = 0; h < 2; ++h) {
            int r = lr + h * 64;
            float4 a4 = *(const float4*)(g_O + (size_t)(row0 + r) * CC + k0 + lc);
            *(float2*)&As2[lc + 0][2 * r] = make_float2(a4.x, a4.x);
            *(float2*)&As2[lc + 1][2 * r] = make_float2(a4.y, a4.y);
            *(float2*)&As2[lc + 2][2 * r] = make_float2(a4.z, a4.z);
            *(float2*)&As2[lc + 3][2 * r] = make_float2(a4.w, a4.w);
        }
#pragma unroll
        for (int h = 0; h < 2; ++h) {
            int kk = (tid >> 5) + h * 8;
            int n  = (tid & 31) * 4;
            *(float4*)&Bs[kk][n] = *(const float4*)(Wo + (size_t)(k0 + kk) * DIMK + col0 + n);
        }
        __syncthreads();
#pragma unroll
        for (int kk = 0; kk < 16; ++kk) {
            const ulonglong2* ap = (const ulonglong2*)&As2[kk][2 * (ty * 8)];
            const ulonglong2* bp = (const ulonglong2*)&Bs[kk][tx * 8];
            ulonglong2 a01 = ap[0], a23 = ap[1], a45 = ap[2], a67 = ap[3];
            ulonglong2 b01 = bp[0], b23 = bp[1];
            ull ar[8] = {a01.x, a01.y, a23.x, a23.y, a45.x, a45.y, a67.x, a67.y};
            ull br[4] = {b01.x, b01.y, b23.x, b23.y};
#pragma unroll
            for (int m = 0; m < 8; ++m)
#pragma unroll
                for (int n = 0; n < 4; ++n)
                    acc[m][n] = fma2(ar[m], br[n], acc[m][n]);
        }
        __syncthreads();
    }

#pragma unroll
    for (int m = 0; m < 8; ++m) {
        int row = row0 + ty * 8 + m;
#pragma unroll
        for (int n = 0; n < 4; ++n) {
            int col = col0 + tx * 8 + 2 * n;
            float e0, e1; unpack2(acc[m][n], e0, e1);
            *(float2*)&out[(size_t)row * DIMK + col] =
                make_float2(e0 + bo[col], e1 + bo[col + 1]);
        }
    }
}

// ===========================================================================
extern "C" void kernel_launch(void* const* d_in, const int* in_sizes, int n_in,
                              void* d_out, int out_size)
{
    const float* x  = (const float*)d_in[0];
    const float* Wq = (const float*)d_in[1];  const float* bq = (const float*)d_in[2];
    const float* Wk = (const float*)d_in[3];  const float* bk = (const float*)d_in[4];
    const float* Wv = (const float*)d_in[5];  const float* bv = (const float*)d_in[6];
    const float* Wa = (const float*)d_in[7];  const float* ba = (const float*)d_in[8];
    const float* Wb = (const float*)d_in[9];  const float* bb = (const float*)d_in[10];
    const float* Wg = (const float*)d_in[11]; const float* bg = (const float*)d_in[12];
    const float* Wo = (const float*)d_in[13]; const float* bo = (const float*)d_in[14];
    float* out = (float*)d_out;

    proj_gemm<<<dim3(128, 4), 256>>>(x, Wq, Wk, Wv, Wg, bq, bk, bv, bg);
    ab_kernel<<<2048, 256>>>(x, Wa, ba, Wb, bb);
    knorm_kernel<<<2048, 256>>>();
    scan_kernel<<<BB, 512>>>();
    out_gemm<<<dim3(128, 8), 256>>>(Wo, bo, out);
}

// round 5
// speedup vs baseline: 1.5050x; 1.5050x over previous
#include <cuda_runtime.h>
#include <cuda_bf16.h>
#include <math.h>

#define DIMK 1024
#define CC   128
#define BB   8
#define TT   2048
#define ROWS (BB*TT)   // 16384

typedef unsigned long long ull;

// ------------------------- device scratch (no allocs allowed) -------------
__device__ float g_Q [ROWS*CC];
__device__ float g_K [ROWS*CC];   // normalized k
__device__ float g_V [ROWS*CC];
__device__ float g_G [ROWS*CC];
__device__ float g_O [ROWS*CC];
__device__ float g_Al[ROWS];
__device__ float g_Be[ROWS];

__device__ __forceinline__ float sigmoidf_(float x) { return 1.0f / (1.0f + expf(-x)); }

// ---- packed f32x2 helpers ----
__device__ __forceinline__ ull pack2(float lo, float hi) {
    ull r; asm("mov.b64 %0, {%1, %2};" : "=l"(r) : "f"(lo), "f"(hi)); return r;
}
__device__ __forceinline__ void unpack2(ull v, float& lo, float& hi) {
    asm("mov.b64 {%0, %1}, %2;" : "=f"(lo), "=f"(hi) : "l"(v));
}
__device__ __forceinline__ ull fma2(ull a, ull b, ull c) {
    ull d; asm("fma.rn.f32x2 %0, %1, %2, %3;" : "=l"(d) : "l"(a), "l"(b), "l"(c)); return d;
}
__device__ __forceinline__ ull mul2(ull a, ull b) {
    ull d; asm("mul.rn.f32x2 %0, %1, %2;" : "=l"(d) : "l"(a), "l"(b)); return d;
}

// ===========================================================================
// Kernel 1: projections  q,k,v,g = x @ W + b  (f32x2 SGEMM, 128x128x16)
// with register double-buffering of global loads.
// ===========================================================================
__global__ __launch_bounds__(256) void proj_gemm(
    const float* __restrict__ x,
    const float* __restrict__ Wq, const float* __restrict__ Wk,
    const float* __restrict__ Wv, const float* __restrict__ Wg,
    const float* __restrict__ bq, const float* __restrict__ bk,
    const float* __restrict__ bv, const float* __restrict__ bg)
{
    __shared__ __align__(16) float As2[16][256];
    __shared__ __align__(16) float Bs[16][128];

    const int mid  = blockIdx.y;
    const float* W    = (mid == 0) ? Wq : (mid == 1) ? Wk : (mid == 2) ? Wv : Wg;
    const float* bias = (mid == 0) ? bq : (mid == 1) ? bk : (mid == 2) ? bv : bg;
    float* outp       = (mid == 0) ? g_Q : (mid == 1) ? g_K : (mid == 2) ? g_V : g_G;

    const int row0 = blockIdx.x * 128;
    const int tid  = threadIdx.x;
    const int tx   = tid & 15;
    const int ty   = tid >> 4;
    const int lr   = tid >> 2;
    const int lc   = (tid & 3) * 4;
    const int bkk  = tid >> 5;
    const int bn   = (tid & 31) * 4;

    ull acc[8][4];
#pragma unroll
    for (int m = 0; m < 8; ++m)
#pragma unroll
        for (int n = 0; n < 4; ++n) acc[m][n] = 0ull;

    float4 aR[2], bR[2];
#pragma unroll
    for (int h = 0; h < 2; ++h) {
        aR[h] = *(const float4*)(x + (size_t)(row0 + lr + h * 64) * DIMK + lc);
        bR[h] = *(const float4*)(W + (size_t)(bkk + h * 8) * CC + bn);
    }

    for (int k0 = 0; k0 < DIMK; k0 += 16) {
#pragma unroll
        for (int h = 0; h < 2; ++h) {
            int r = lr + h * 64;
            *(float2*)&As2[lc + 0][2 * r] = make_float2(aR[h].x, aR[h].x);
            *(float2*)&As2[lc + 1][2 * r] = make_float2(aR[h].y, aR[h].y);
            *(float2*)&As2[lc + 2][2 * r] = make_float2(aR[h].z, aR[h].z);
            *(float2*)&As2[lc + 3][2 * r] = make_float2(aR[h].w, aR[h].w);
            *(float4*)&Bs[bkk + h * 8][bn] = bR[h];
        }
        __syncthreads();

        if (k0 + 16 < DIMK) {
#pragma unroll
            for (int h = 0; h < 2; ++h) {
                aR[h] = *(const float4*)(x + (size_t)(row0 + lr + h * 64) * DIMK + k0 + 16 + lc);
                bR[h] = *(const float4*)(W + (size_t)(k0 + 16 + bkk + h * 8) * CC + bn);
            }
        }
#pragma unroll
        for (int kk = 0; kk < 16; ++kk) {
            const ulonglong2* ap = (const ulonglong2*)&As2[kk][2 * (ty * 8)];
            const ulonglong2* bp = (const ulonglong2*)&Bs[kk][tx * 8];
            ulonglong2 a01 = ap[0], a23 = ap[1], a45 = ap[2], a67 = ap[3];
            ulonglong2 b01 = bp[0], b23 = bp[1];
            ull ar[8] = {a01.x, a01.y, a23.x, a23.y, a45.x, a45.y, a67.x, a67.y};
            ull br[4] = {b01.x, b01.y, b23.x, b23.y};
#pragma unroll
            for (int m = 0; m < 8; ++m)
#pragma unroll
                for (int n = 0; n < 4; ++n)
                    acc[m][n] = fma2(ar[m], br[n], acc[m][n]);
        }
        __syncthreads();
    }

#pragma unroll
    for (int m = 0; m < 8; ++m) {
        int row = row0 + ty * 8 + m;
#pragma unroll
        for (int n = 0; n < 4; ++n) {
            int col = tx * 8 + 2 * n;
            float e0, e1; unpack2(acc[m][n], e0, e1);
            float v0 = e0 + bias[col];
            float v1 = e1 + bias[col + 1];
            if (mid == 3) { v0 = sigmoidf_(v0); v1 = sigmoidf_(v1); }
            *(float2*)&outp[(size_t)row * CC + col] = make_float2(v0, v1);
        }
    }
}

// ===========================================================================
// Kernel 2: alpha/beta
// ===========================================================================
__global__ __launch_bounds__(256) void ab_kernel(
    const float* __restrict__ x,
    const float* __restrict__ Wa, const float* __restrict__ ba,
    const float* __restrict__ Wb, const float* __restrict__ bb)
{
    const int warp = threadIdx.x >> 5, lane = threadIdx.x & 31;
    const int row  = blockIdx.x * 8 + warp;
    const float* xr = x + (size_t)row * DIMK;
    float accA = 0.0f, accB = 0.0f;
#pragma unroll
    for (int it = 0; it < 8; ++it) {
        int kidx = it * 128 + lane * 4;
        float4 xv = *(const float4*)(xr + kidx);
        float4 wa = *(const float4*)(Wa + kidx);
        float4 wb = *(const float4*)(Wb + kidx);
        accA += xv.x * wa.x + xv.y * wa.y + xv.z * wa.z + xv.w * wa.w;
        accB += xv.x * wb.x + xv.y * wb.y + xv.z * wb.z + xv.w * wb.w;
    }
#pragma unroll
    for (int o = 16; o; o >>= 1) {
        accA += __shfl_xor_sync(0xffffffffu, accA, o);
        accB += __shfl_xor_sync(0xffffffffu, accB, o);
    }
    if (lane == 0) {
        g_Al[row] = sigmoidf_(accA + ba[0]);
        g_Be[row] = sigmoidf_(accB + bb[0]);
    }
}

// ===========================================================================
// Kernel 3: normalize k rows
// ===========================================================================
__global__ __launch_bounds__(256) void knorm_kernel()
{
    const int warp = threadIdx.x >> 5, lane = threadIdx.x & 31;
    const int row  = blockIdx.x * 8 + warp;
    float* kp = g_K + (size_t)row * CC + lane * 4;
    float4 kv = *(float4*)kp;
    float ss = kv.x * kv.x + kv.y * kv.y + kv.z * kv.z + kv.w * kv.w;
#pragma unroll
    for (int o = 16; o; o >>= 1) ss += __shfl_xor_sync(0xffffffffu, ss, o);
    float scale = 1.0f / fmaxf(sqrtf(ss), 1e-12f);
    kv.x *= scale; kv.y *= scale; kv.z *= scale; kv.w *= scale;
    *(float4*)kp = kv;
}

// ===========================================================================
// Kernel 4: gated-delta scan, one CTA (256 threads) per batch.
// A threads (0..127): own row i of S_hat in regs (64 ull).
// B threads (128..255): own row j of S_hat^T; fuse update+output dot.
// Producer->consumer: A bar.arrive after writing u; B bar.sync — A never
// waits for B mid-step. S_true = c*S_hat, c block-uniform.
// ===========================================================================
__global__ __launch_bounds__(256, 1) void scan_kernel()
{
    const int b    = blockIdx.x;
    const int tid  = threadIdx.x;
    const bool isA = (tid < 128);
    const int  r   = tid & 127;

    __shared__ __align__(16) float k_sh[2][128], q_sh[2][128];
    __shared__ __align__(16) float v_sh[2][128], g_sh[2][128];
    __shared__ __align__(16) float u_sh[128];
    __shared__ float2 ab_sh[2];

    ull Sp[64];
#pragma unroll
    for (int j = 0; j < 64; ++j) Sp[j] = 0ull;
    float c = 1.0f;

    const size_t base = (size_t)b * TT * CC;
    const float* Qb = g_Q + base;
    const float* Kb = g_K + base;
    const float* Vb = g_V + base;
    const float* Gb = g_G + base;
    const float* Ab = g_Al + (size_t)b * TT;
    const float* Bb = g_Be + (size_t)b * TT;
    float*       Ob = g_O + base;

    // preload t=0
    float s0, s1;
    if (isA) { s0 = Kb[r]; s1 = Qb[r]; }
    else     { s0 = Vb[r]; s1 = Gb[r]; }
    float2 abr = make_float2(0.f, 0.f);
    if (tid == 0) abr = make_float2(Ab[0], Bb[0]);

    int p = 0;
    for (int t = 0; t < TT; ++t) {
        if (isA) { k_sh[p][r] = s0; q_sh[p][r] = s1; }
        else     { v_sh[p][r] = s0; g_sh[p][r] = s1; }
        if (tid == 0) ab_sh[p] = abr;
        __syncthreads();

        // prefetch t+1 (issued before any waiting)
        if (t + 1 < TT) {
            const size_t off = (size_t)(t + 1) * CC + r;
            if (isA) { s0 = Kb[off]; s1 = Qb[off]; }
            else     { s0 = Vb[off]; s1 = Gb[off]; }
            if (tid == 0) abr = make_float2(Ab[t + 1], Bb[t + 1]);
        }

        const float aa = ab_sh[p].x;
        const float cn = aa * c;

        if (isA) {
            const float bbv = ab_sh[p].y;
            // dot: S_hat[r,:] . k
            const ulonglong2* k16 = (const ulonglong2*)k_sh[p];
            ull a0 = 0ull, a1 = 0ull, a2 = 0ull, a3 = 0ull;
#pragma unroll
            for (int j = 0; j < 16; ++j) {
                ulonglong2 xa = k16[2 * j], xb = k16[2 * j + 1];
                a0 = fma2(Sp[4 * j + 0], xa.x, a0);
                a1 = fma2(Sp[4 * j + 1], xa.y, a1);
                a2 = fma2(Sp[4 * j + 2], xb.x, a2);
                a3 = fma2(Sp[4 * j + 3], xb.y, a3);
            }
            float f0, f1, f2, f3, f4, f5, f6, f7;
            unpack2(a0, f0, f1); unpack2(a1, f2, f3);
            unpack2(a2, f4, f5); unpack2(a3, f6, f7);
            const float dot = ((f0 + f1) + (f2 + f3)) + ((f4 + f5) + (f6 + f7));

            const float u = bbv * v_sh[p][r] - aa * bbv * (c * dot);
            u_sh[r] = u;
            asm volatile("bar.arrive 1, 256;" ::: "memory");

            // S_hat[r,:] += (u/cn) * k
            const float w = u * (1.0f / cn);
            const ull w2 = pack2(w, w);
#pragma unroll
            for (int j = 0; j < 16; ++j) {
                ulonglong2 ka = k16[2 * j], kb = k16[2 * j + 1];
                Sp[4 * j + 0] = fma2(w2, ka.x, Sp[4 * j + 0]);
                Sp[4 * j + 1] = fma2(w2, ka.y, Sp[4 * j + 1]);
                Sp[4 * j + 2] = fma2(w2, kb.x, Sp[4 * j + 2]);
                Sp[4 * j + 3] = fma2(w2, kb.y, Sp[4 * j + 3]);
            }
        } else {
            asm volatile("bar.sync 1, 256;" ::: "memory");
            // fused: S_hat^T[r,:] += (k_r/cn)*u ; ohat = S_hat^T_new[r,:].q
            const float kj   = k_sh[p][r];
            const float kw   = kj * (1.0f / cn);
            const ull   kw2  = pack2(kw, kw);
            const ulonglong2* u16 = (const ulonglong2*)u_sh;
            const ulonglong2* q16 = (const ulonglong2*)q_sh[p];
            ull o0 = 0ull, o1 = 0ull, o2 = 0ull, o3 = 0ull;
#pragma unroll
            for (int j = 0; j < 16; ++j) {
                ulonglong2 ua = u16[2 * j], ub = u16[2 * j + 1];
                ulonglong2 qa = q16[2 * j], qb = q16[2 * j + 1];
                Sp[4 * j + 0] = fma2(kw2, ua.x, Sp[4 * j + 0]);
                o0 = fma2(Sp[4 * j + 0], qa.x, o0);
                Sp[4 * j + 1] = fma2(kw2, ua.y, Sp[4 * j + 1]);
                o1 = fma2(Sp[4 * j + 1], qa.y, o1);
                Sp[4 * j + 2] = fma2(kw2, ub.x, Sp[4 * j + 2]);
                o2 = fma2(Sp[4 * j + 2], qb.x, o2);
                Sp[4 * j + 3] = fma2(kw2, ub.y, Sp[4 * j + 3]);
                o3 = fma2(Sp[4 * j + 3], qb.y, o3);
            }
            float f0, f1, f2, f3, f4, f5, f6, f7;
            unpack2(o0, f0, f1); unpack2(o1, f2, f3);
            unpack2(o2, f4, f5); unpack2(o3, f6, f7);
            const float ohat = ((f0 + f1) + (f2 + f3)) + ((f4 + f5) + (f6 + f7));
            Ob[(size_t)t * CC + r] = (cn * ohat) * g_sh[p][r];
        }

        c = cn;
        if (c < 1e-10f) {
            const ull c2 = pack2(c, c);
#pragma unroll
            for (int j = 0; j < 64; ++j) Sp[j] = mul2(Sp[j], c2);
            c = 1.0f;
        }
        p ^= 1;
    }
}

// ===========================================================================
// Kernel 5: out = O @ Wo + bo   (f32x2 SGEMM, prefetched)
// ===========================================================================
__global__ __launch_bounds__(256) void out_gemm(
    const float* __restrict__ Wo, const float* __restrict__ bo,
    float* __restrict__ out)
{
    __shared__ __align__(16) float As2[16][256];
    __shared__ __align__(16) float Bs[16][128];

    const int row0 = blockIdx.x * 128;
    const int col0 = blockIdx.y * 128;
    const int tid  = threadIdx.x;
    const int tx   = tid & 15;
    const int ty   = tid >> 4;
    const int lr   = tid >> 2;
    const int lc   = (tid & 3) * 4;
    const int bkk  = tid >> 5;
    const int bn   = (tid & 31) * 4;

    ull acc[8][4];
#pragma unroll
    for (int m = 0; m < 8; ++m)
#pragma unroll
        for (int n = 0; n < 4; ++n) acc[m][n] = 0ull;

    float4 aR[2], bR[2];
#pragma unroll
    for (int h = 0; h < 2; ++h) {
        aR[h] = *(const float4*)(g_O + (size_t)(row0 + lr + h * 64) * CC + lc);
        bR[h] = *(const float4*)(Wo + (size_t)(bkk + h * 8) * DIMK + col0 + bn);
    }

    for (int k0 = 0; k0 < CC; k0 += 16) {
#pragma unroll
        for (int h = 0; h < 2; ++h) {
            int r = lr + h * 64;
            *(float2*)&As2[lc + 0][2 * r] = make_float2(aR[h].x, aR[h].x);
            *(float2*)&As2[lc + 1][2 * r] = make_float2(aR[h].y, aR[h].y);
            *(float2*)&As2[lc + 2][2 * r] = make_float2(aR[h].z, aR[h].z);
            *(float2*)&As2[lc + 3][2 * r] = make_float2(aR[h].w, aR[h].w);
            *(float4*)&Bs[bkk + h * 8][bn] = bR[h];
        }
        __syncthreads();

        if (k0 + 16 < CC) {
#pragma unroll
            for (int h = 0; h < 2; ++h) {
                aR[h] = *(const float4*)(g_O + (size_t)(row0 + lr + h * 64) * CC + k0 + 16 + lc);
                bR[h] = *(const float4*)(Wo + (size_t)(k0 + 16 + bkk + h * 8) * DIMK + col0 + bn);
            }
        }
#pragma unroll
        for (int kk = 0; kk < 16; ++kk) {
            const ulonglong2* ap = (const ulonglong2*)&As2[kk][2 * (ty * 8)];
            const ulonglong2* bp = (const ulonglong2*)&Bs[kk][tx * 8];
            ulonglong2 a01 = ap[0], a23 = ap[1], a45 = ap[2], a67 = ap[3];
            ulonglong2 b01 = bp[0], b23 = bp[1];
            ull ar[8] = {a01.x, a01.y, a23.x, a23.y, a45.x, a45.y, a67.x, a67.y};
            ull br[4] = {b01.x, b01.y, b23.x, b23.y};
#pragma unroll
            for (int m = 0; m < 8; ++m)
#pragma unroll
                for (int n = 0; n < 4; ++n)
                    acc[m][n] = fma2(ar[m], br[n], acc[m][n]);
        }
        __syncthreads();
    }

#pragma unroll
    for (int m = 0; m < 8; ++m) {
        int row = row0 + ty * 8 + m;
#pragma unroll
        for (int n = 0; n < 4; ++n) {
            int col = col0 + tx * 8 + 2 * n;
            float e0, e1; unpack2(acc[m][n], e0, e1);
            *(float2*)&out[(size_t)row * DIMK + col] =
                make_float2(e0 + bo[col], e1 + bo[col + 1]);
        }
    }
}

// ===========================================================================
extern "C" void kernel_launch(void* const* d_in, const int* in_sizes, int n_in,
                              void* d_out, int out_size)
{
    const float* x  = (const float*)d_in[0];
    const float* Wq = (const float*)d_in[1];  const float* bq = (const float*)d_in[2];
    const float* Wk = (const float*)d_in[3];  const float* bk = (const float*)d_in[4];
    const float* Wv = (const float*)d_in[5];  const float* bv = (const float*)d_in[6];
    const float* Wa = (const float*)d_in[7];  const float* ba = (const float*)d_in[8];
    const float* Wb = (const float*)d_in[9];  const float* bb = (const float*)d_in[10];
    const float* Wg = (const float*)d_in[11]; const float* bg = (const float*)d_in[12];
    const float* Wo = (const float*)d_in[13]; const float* bo = (const float*)d_in[14];
    float* out = (float*)d_out;

    proj_gemm<<<dim3(128, 4), 256>>>(x, Wq, Wk, Wv, Wg, bq, bk, bv, bg);
    ab_kernel<<<2048, 256>>>(x, Wa, ba, Wb, bb);
    knorm_kernel<<<2048, 256>>>();
    scan_kernel<<<BB, 256>>>();
    out_gemm<<<dim3(128, 8), 256>>>(Wo, bo, out);
}

// round 6
// speedup vs baseline: 1.5070x; 1.0014x over previous
#include <cuda_runtime.h>
#include <cuda_bf16.h>
#include <math.h>

#define DIMK 1024
#define CC   128
#define BB   8
#define TT   2048
#define ROWS (BB*TT)   // 16384

typedef unsigned long long ull;

// ------------------------- device scratch (no allocs allowed) -------------
__device__ float g_Q [ROWS*CC];
__device__ float g_K [ROWS*CC];   // normalized k
__device__ float g_V [ROWS*CC];
__device__ float g_G [ROWS*CC];
__device__ float g_O [ROWS*CC];
__device__ float g_Al[ROWS];
__device__ float g_Be[ROWS];

__device__ __forceinline__ float sigmoidf_(float x) { return 1.0f / (1.0f + expf(-x)); }

// ---- packed f32x2 helpers ----
__device__ __forceinline__ ull pack2(float lo, float hi) {
    ull r; asm("mov.b64 %0, {%1, %2};" : "=l"(r) : "f"(lo), "f"(hi)); return r;
}
__device__ __forceinline__ void unpack2(ull v, float& lo, float& hi) {
    asm("mov.b64 {%0, %1}, %2;" : "=f"(lo), "=f"(hi) : "l"(v));
}
__device__ __forceinline__ ull fma2(ull a, ull b, ull c) {
    ull d; asm("fma.rn.f32x2 %0, %1, %2, %3;" : "=l"(d) : "l"(a), "l"(b), "l"(c)); return d;
}
__device__ __forceinline__ ull mul2(ull a, ull b) {
    ull d; asm("mul.rn.f32x2 %0, %1, %2;" : "=l"(d) : "l"(a), "l"(b)); return d;
}

// ===========================================================================
// Kernel 1: projections  q,k,v,g = x @ W + b  (f32x2 SGEMM, 128x128x16)
// with register double-buffering of global loads.
// ===========================================================================
__global__ __launch_bounds__(256) void proj_gemm(
    const float* __restrict__ x,
    const float* __restrict__ Wq, const float* __restrict__ Wk,
    const float* __restrict__ Wv, const float* __restrict__ Wg,
    const float* __restrict__ bq, const float* __restrict__ bk,
    const float* __restrict__ bv, const float* __restrict__ bg)
{
    __shared__ __align__(16) float As2[16][256];
    __shared__ __align__(16) float Bs[16][128];

    const int mid  = blockIdx.y;
    const float* W    = (mid == 0) ? Wq : (mid == 1) ? Wk : (mid == 2) ? Wv : Wg;
    const float* bias = (mid == 0) ? bq : (mid == 1) ? bk : (mid == 2) ? bv : bg;
    float* outp       = (mid == 0) ? g_Q : (mid == 1) ? g_K : (mid == 2) ? g_V : g_G;

    const int row0 = blockIdx.x * 128;
    const int tid  = threadIdx.x;
    const int tx   = tid & 15;
    const int ty   = tid >> 4;
    const int lr   = tid >> 2;
    const int lc   = (tid & 3) * 4;
    const int bkk  = tid >> 5;
    const int bn   = (tid & 31) * 4;

    ull acc[8][4];
#pragma unroll
    for (int m = 0; m < 8; ++m)
#pragma unroll
        for (int n = 0; n < 4; ++n) acc[m][n] = 0ull;

    float4 aR[2], bR[2];
#pragma unroll
    for (int h = 0; h < 2; ++h) {
        aR[h] = *(const float4*)(x + (size_t)(row0 + lr + h * 64) * DIMK + lc);
        bR[h] = *(const float4*)(W + (size_t)(bkk + h * 8) * CC + bn);
    }

    for (int k0 = 0; k0 < DIMK; k0 += 16) {
#pragma unroll
        for (int h = 0; h < 2; ++h) {
            int r = lr + h * 64;
            *(float2*)&As2[lc + 0][2 * r] = make_float2(aR[h].x, aR[h].x);
            *(float2*)&As2[lc + 1][2 * r] = make_float2(aR[h].y, aR[h].y);
            *(float2*)&As2[lc + 2][2 * r] = make_float2(aR[h].z, aR[h].z);
            *(float2*)&As2[lc + 3][2 * r] = make_float2(aR[h].w, aR[h].w);
            *(float4*)&Bs[bkk + h * 8][bn] = bR[h];
        }
        __syncthreads();

        if (k0 + 16 < DIMK) {
#pragma unroll
            for (int h = 0; h < 2; ++h) {
                aR[h] = *(const float4*)(x + (size_t)(row0 + lr + h * 64) * DIMK + k0 + 16 + lc);
                bR[h] = *(const float4*)(W + (size_t)(k0 + 16 + bkk + h * 8) * CC + bn);
            }
        }
#pragma unroll
        for (int kk = 0; kk < 16; ++kk) {
            const ulonglong2* ap = (const ulonglong2*)&As2[kk][2 * (ty * 8)];
            const ulonglong2* bp = (const ulonglong2*)&Bs[kk][tx * 8];
            ulonglong2 a01 = ap[0], a23 = ap[1], a45 = ap[2], a67 = ap[3];
            ulonglong2 b01 = bp[0], b23 = bp[1];
            ull ar[8] = {a01.x, a01.y, a23.x, a23.y, a45.x, a45.y, a67.x, a67.y};
            ull br[4] = {b01.x, b01.y, b23.x, b23.y};
#pragma unroll
            for (int m = 0; m < 8; ++m)
#pragma unroll
                for (int n = 0; n < 4; ++n)
                    acc[m][n] = fma2(ar[m], br[n], acc[m][n]);
        }
        __syncthreads();
    }

#pragma unroll
    for (int m = 0; m < 8; ++m) {
        int row = row0 + ty * 8 + m;
#pragma unroll
        for (int n = 0; n < 4; ++n) {
            int col = tx * 8 + 2 * n;
            float e0, e1; unpack2(acc[m][n], e0, e1);
            float v0 = e0 + bias[col];
            float v1 = e1 + bias[col + 1];
            if (mid == 3) { v0 = sigmoidf_(v0); v1 = sigmoidf_(v1); }
            *(float2*)&outp[(size_t)row * CC + col] = make_float2(v0, v1);
        }
    }
}

// ===========================================================================
// Kernel 2: alpha/beta
// ===========================================================================
__global__ __launch_bounds__(256) void ab_kernel(
    const float* __restrict__ x,
    const float* __restrict__ Wa, const float* __restrict__ ba,
    const float* __restrict__ Wb, const float* __restrict__ bb)
{
    const int warp = threadIdx.x >> 5, lane = threadIdx.x & 31;
    const int row  = blockIdx.x * 8 + warp;
    const float* xr = x + (size_t)row * DIMK;
    float accA = 0.0f, accB = 0.0f;
#pragma unroll
    for (int it = 0; it < 8; ++it) {
        int kidx = it * 128 + lane * 4;
        float4 xv = *(const float4*)(xr + kidx);
        float4 wa = *(const float4*)(Wa + kidx);
        float4 wb = *(const float4*)(Wb + kidx);
        accA += xv.x * wa.x + xv.y * wa.y + xv.z * wa.z + xv.w * wa.w;
        accB += xv.x * wb.x + xv.y * wb.y + xv.z * wb.z + xv.w * wb.w;
    }
#pragma unroll
    for (int o = 16; o; o >>= 1) {
        accA += __shfl_xor_sync(0xffffffffu, accA, o);
        accB += __shfl_xor_sync(0xffffffffu, accB, o);
    }
    if (lane == 0) {
        g_Al[row] = sigmoidf_(accA + ba[0]);
        g_Be[row] = sigmoidf_(accB + bb[0]);
    }
}

// ===========================================================================
// Kernel 3: normalize k rows
// ===========================================================================
__global__ __launch_bounds__(256) void knorm_kernel()
{
    const int warp = threadIdx.x >> 5, lane = threadIdx.x & 31;
    const int row  = blockIdx.x * 8 + warp;
    float* kp = g_K + (size_t)row * CC + lane * 4;
    float4 kv = *(float4*)kp;
    float ss = kv.x * kv.x + kv.y * kv.y + kv.z * kv.z + kv.w * kv.w;
#pragma unroll
    for (int o = 16; o; o >>= 1) ss += __shfl_xor_sync(0xffffffffu, ss, o);
    float scale = 1.0f / fmaxf(sqrtf(ss), 1e-12f);
    kv.x *= scale; kv.y *= scale; kv.z *= scale; kv.w *= scale;
    *(float4*)kp = kv;
}

// ===========================================================================
// Kernel 4: gated-delta scan, one CTA (256 threads) per batch.
// A threads (0..127): own row i of S_hat in regs (64 ull).
// B threads (128..255): own row j of S_hat^T; fuse update+output dot.
// Producer->consumer: A bar.arrive after writing u; B bar.sync — A never
// waits for B mid-step. S_true = c*S_hat, c block-uniform.
// ===========================================================================
__global__ __launch_bounds__(256, 1) void scan_kernel()
{
    const int b    = blockIdx.x;
    const int tid  = threadIdx.x;
    const bool isA = (tid < 128);
    const int  r   = tid & 127;

    __shared__ __align__(16) float k_sh[2][128], q_sh[2][128];
    __shared__ __align__(16) float v_sh[2][128], g_sh[2][128];
    __shared__ __align__(16) float u_sh[128];
    __shared__ float2 ab_sh[2];

    ull Sp[64];
#pragma unroll
    for (int j = 0; j < 64; ++j) Sp[j] = 0ull;
    float c = 1.0f;

    const size_t base = (size_t)b * TT * CC;
    const float* Qb = g_Q + base;
    const float* Kb = g_K + base;
    const float* Vb = g_V + base;
    const float* Gb = g_G + base;
    const float* Ab = g_Al + (size_t)b * TT;
    const float* Bb = g_Be + (size_t)b * TT;
    float*       Ob = g_O + base;

    // preload t=0
    float s0, s1;
    if (isA) { s0 = Kb[r]; s1 = Qb[r]; }
    else     { s0 = Vb[r]; s1 = Gb[r]; }
    float2 abr = make_float2(0.f, 0.f);
    if (tid == 0) abr = make_float2(Ab[0], Bb[0]);

    int p = 0;
    for (int t = 0; t < TT; ++t) {
        if (isA) { k_sh[p][r] = s0; q_sh[p][r] = s1; }
        else     { v_sh[p][r] = s0; g_sh[p][r] = s1; }
        if (tid == 0) ab_sh[p] = abr;
        __syncthreads();

        // prefetch t+1 (issued before any waiting)
        if (t + 1 < TT) {
            const size_t off = (size_t)(t + 1) * CC + r;
            if (isA) { s0 = Kb[off]; s1 = Qb[off]; }
            else     { s0 = Vb[off]; s1 = Gb[off]; }
            if (tid == 0) abr = make_float2(Ab[t + 1], Bb[t + 1]);
        }

        const float aa = ab_sh[p].x;
        const float cn = aa * c;

        if (isA) {
            const float bbv = ab_sh[p].y;
            // dot: S_hat[r,:] . k
            const ulonglong2* k16 = (const ulonglong2*)k_sh[p];
            ull a0 = 0ull, a1 = 0ull, a2 = 0ull, a3 = 0ull;
#pragma unroll
            for (int j = 0; j < 16; ++j) {
                ulonglong2 xa = k16[2 * j], xb = k16[2 * j + 1];
                a0 = fma2(Sp[4 * j + 0], xa.x, a0);
                a1 = fma2(Sp[4 * j + 1], xa.y, a1);
                a2 = fma2(Sp[4 * j + 2], xb.x, a2);
                a3 = fma2(Sp[4 * j + 3], xb.y, a3);
            }
            float f0, f1, f2, f3, f4, f5, f6, f7;
            unpack2(a0, f0, f1); unpack2(a1, f2, f3);
            unpack2(a2, f4, f5); unpack2(a3, f6, f7);
            const float dot = ((f0 + f1) + (f2 + f3)) + ((f4 + f5) + (f6 + f7));

            const float u = bbv * v_sh[p][r] - aa * bbv * (c * dot);
            u_sh[r] = u;
            asm volatile("bar.arrive 1, 256;" ::: "memory");

            // S_hat[r,:] += (u/cn) * k
            const float w = u * (1.0f / cn);
            const ull w2 = pack2(w, w);
#pragma unroll
            for (int j = 0; j < 16; ++j) {
                ulonglong2 ka = k16[2 * j], kb = k16[2 * j + 1];
                Sp[4 * j + 0] = fma2(w2, ka.x, Sp[4 * j + 0]);
                Sp[4 * j + 1] = fma2(w2, ka.y, Sp[4 * j + 1]);
                Sp[4 * j + 2] = fma2(w2, kb.x, Sp[4 * j + 2]);
                Sp[4 * j + 3] = fma2(w2, kb.y, Sp[4 * j + 3]);
            }
        } else {
            asm volatile("bar.sync 1, 256;" ::: "memory");
            // fused: S_hat^T[r,:] += (k_r/cn)*u ; ohat = S_hat^T_new[r,:].q
            const float kj   = k_sh[p][r];
            const float kw   = kj * (1.0f / cn);
            const ull   kw2  = pack2(kw, kw);
            const ulonglong2* u16 = (const ulonglong2*)u_sh;
            const ulonglong2* q16 = (const ulonglong2*)q_sh[p];
            ull o0 = 0ull, o1 = 0ull, o2 = 0ull, o3 = 0ull;
#pragma unroll
            for (int j = 0; j < 16; ++j) {
                ulonglong2 ua = u16[2 * j], ub = u16[2 * j + 1];
                ulonglong2 qa = q16[2 * j], qb = q16[2 * j + 1];
                Sp[4 * j + 0] = fma2(kw2, ua.x, Sp[4 * j + 0]);
                o0 = fma2(Sp[4 * j + 0], qa.x, o0);
                Sp[4 * j + 1] = fma2(kw2, ua.y, Sp[4 * j + 1]);
                o1 = fma2(Sp[4 * j + 1], qa.y, o1);
                Sp[4 * j + 2] = fma2(kw2, ub.x, Sp[4 * j + 2]);
                o2 = fma2(Sp[4 * j + 2], qb.x, o2);
                Sp[4 * j + 3] = fma2(kw2, ub.y, Sp[4 * j + 3]);
                o3 = fma2(Sp[4 * j + 3], qb.y, o3);
            }
            float f0, f1, f2, f3, f4, f5, f6, f7;
            unpack2(o0, f0, f1); unpack2(o1, f2, f3);
            unpack2(o2, f4, f5); unpack2(o3, f6, f7);
            const float ohat = ((f0 + f1) + (f2 + f3)) + ((f4 + f5) + (f6 + f7));
            Ob[(size_t)t * CC + r] = (cn * ohat) * g_sh[p][r];
        }

        c = cn;
        if (c < 1e-10f) {
            const ull c2 = pack2(c, c);
#pragma unroll
            for (int j = 0; j < 64; ++j) Sp[j] = mul2(Sp[j], c2);
            c = 1.0f;
        }
        p ^= 1;
    }
}

// ===========================================================================
// Kernel 5: out = O @ Wo + bo   (f32x2 SGEMM, prefetched)
// ===========================================================================
__global__ __launch_bounds__(256) void out_gemm(
    const float* __restrict__ Wo, const float* __restrict__ bo,
    float* __restrict__ out)
{
    __shared__ __align__(16) float As2[16][256];
    __shared__ __align__(16) float Bs[16][128];

    const int row0 = blockIdx.x * 128;
    const int col0 = blockIdx.y * 128;
    const int tid  = threadIdx.x;
    const int tx   = tid & 15;
    const int ty   = tid >> 4;
    const int lr   = tid >> 2;
    const int lc   = (tid & 3) * 4;
    const int bkk  = tid >> 5;
    const int bn   = (tid & 31) * 4;

    ull acc[8][4];
#pragma unroll
    for (int m = 0; m < 8; ++m)
#pragma unroll
        for (int n = 0; n < 4; ++n) acc[m][n] = 0ull;

    float4 aR[2], bR[2];
#pragma unroll
    for (int h = 0; h < 2; ++h) {
        aR[h] = *(const float4*)(g_O + (size_t)(row0 + lr + h * 64) * CC + lc);
        bR[h] = *(const float4*)(Wo + (size_t)(bkk + h * 8) * DIMK + col0 + bn);
    }

    for (int k0 = 0; k0 < CC; k0 += 16) {
#pragma unroll
        for (int h = 0; h < 2; ++h) {
            int r = lr + h * 64;
            *(float2*)&As2[lc + 0][2 * r] = make_float2(aR[h].x, aR[h].x);
            *(float2*)&As2[lc + 1][2 * r] = make_float2(aR[h].y, aR[h].y);
            *(float2*)&As2[lc + 2][2 * r] = make_float2(aR[h].z, aR[h].z);
            *(float2*)&As2[lc + 3][2 * r] = make_float2(aR[h].w, aR[h].w);
            *(float4*)&Bs[bkk + h * 8][bn] = bR[h];
        }
        __syncthreads();

        if (k0 + 16 < CC) {
#pragma unroll
            for (int h = 0; h < 2; ++h) {
                aR[h] = *(const float4*)(g_O + (size_t)(row0 + lr + h * 64) * CC + k0 + 16 + lc);
                bR[h] = *(const float4*)(Wo + (size_t)(k0 + 16 + bkk + h * 8) * DIMK + col0 + bn);
            }
        }
#pragma unroll
        for (int kk = 0; kk < 16; ++kk) {
            const ulonglong2* ap = (const ulonglong2*)&As2[kk][2 * (ty * 8)];
            const ulonglong2* bp = (const ulonglong2*)&Bs[kk][tx * 8];
            ulonglong2 a01 = ap[0], a23 = ap[1], a45 = ap[2], a67 = ap[3];
            ulonglong2 b01 = bp[0], b23 = bp[1];
            ull ar[8] = {a01.x, a01.y, a23.x, a23.y, a45.x, a45.y, a67.x, a67.y};
            ull br[4] = {b01.x, b01.y, b23.x, b23.y};
#pragma unroll
            for (int m = 0; m < 8; ++m)
#pragma unroll
                for (int n = 0; n < 4; ++n)
                    acc[m][n] = fma2(ar[m], br[n], acc[m][n]);
        }
        __syncthreads();
    }

#pragma unroll
    for (int m = 0; m < 8; ++m) {
        int row = row0 + ty * 8 + m;
#pragma unroll
        for (int n = 0; n < 4; ++n) {
            int col = col0 + tx * 8 + 2 * n;
            float e0, e1; unpack2(acc[m][n], e0, e1);
            *(float2*)&out[(size_t)row * DIMK + col] =
                make_float2(e0 + bo[col], e1 + bo[col + 1]);
        }
    }
}

// ===========================================================================
extern "C" void kernel_launch(void* const* d_in, const int* in_sizes, int n_in,
                              void* d_out, int out_size)
{
    const float* x  = (const float*)d_in[0];
    const float* Wq = (const float*)d_in[1];  const float* bq = (const float*)d_in[2];
    const float* Wk = (const float*)d_in[3];  const float* bk = (const float*)d_in[4];
    const float* Wv = (const float*)d_in[5];  const float* bv = (const float*)d_in[6];
    const float* Wa = (const float*)d_in[7];  const float* ba = (const float*)d_in[8];
    const float* Wb = (const float*)d_in[9];  const float* bb = (const float*)d_in[10];
    const float* Wg = (const float*)d_in[11]; const float* bg = (const float*)d_in[12];
    const float* Wo = (const float*)d_in[13]; const float* bo = (const float*)d_in[14];
    float* out = (float*)d_out;

    proj_gemm<<<dim3(128, 4), 256>>>(x, Wq, Wk, Wv, Wg, bq, bk, bv, bg);
    ab_kernel<<<2048, 256>>>(x, Wa, ba, Wb, bb);
    knorm_kernel<<<2048, 256>>>();
    scan_kernel<<<BB, 256>>>();
    out_gemm<<<dim3(128, 8), 256>>>(Wo, bo, out);
}